// round 1
// baseline (speedup 1.0000x reference)
#include <cuda_runtime.h>
#include <math.h>

#define BB 16
#define SS 1024
#define DD 512
#define NN 2048

#define RCTAS 64
#define RTHREADS 512   // 16 warps; each warp: 2 rows x 16 batches

// ---------------- device scratch (no allocations allowed) ----------------
__device__ float2   g_ent[(size_t)NN * (size_t)NN + 8]; // CSR entries {val, idx-as-float-bits}
__device__ int      g_nnz[NN];
__device__ int      g_rowptr[NN + 1];
__device__ float    g_state[2][NN * BB];                // [buf][n*16+b]
__device__ unsigned g_barrier;

// ---------------- init: reset barrier, transpose initial state ----------------
__global__ void init_kernel(const float* __restrict__ init_state) {
    int i = blockIdx.x * blockDim.x + threadIdx.x;
    if (i == 0) g_barrier = 0u;
    if (i < NN * BB) {
        int b = i & (BB - 1);
        int n = i >> 4;
        g_state[0][i] = init_state[(size_t)b * NN + n];
    }
}

// ---------------- count nnz per row (warp per row, ballot) ----------------
__global__ void count_kernel(const float* __restrict__ W) {
    int gw   = (blockIdx.x * blockDim.x + threadIdx.x) >> 5;
    int lane = threadIdx.x & 31;
    if (gw >= NN) return;
    const float* row = W + (size_t)gw * NN;
    int c = 0;
    for (int m0 = 0; m0 < NN; m0 += 32) {
        float w = row[m0 + lane];
        unsigned msk = __ballot_sync(0xffffffffu, w != 0.0f);
        c += __popc(msk);
    }
    if (lane == 0) g_nnz[gw] = c;
}

// ---------------- exclusive scan over 2048 row counts (1 block) ----------------
__global__ void scan_kernel() {
    __shared__ int sb[2][NN];
    int t = threadIdx.x;
    sb[0][t]        = g_nnz[t];
    sb[0][t + 1024] = g_nnz[t + 1024];
    __syncthreads();
    int cur = 0;
    for (int d = 1; d < NN; d <<= 1) {
        for (int k = t; k < NN; k += 1024) {
            int v = sb[cur][k];
            if (k >= d) v += sb[cur][k - d];
            sb[cur ^ 1][k] = v;
        }
        __syncthreads();
        cur ^= 1;
    }
    if (t == 0) g_rowptr[0] = 0;
    g_rowptr[t + 1]        = sb[cur][t];
    g_rowptr[t + 1 + 1024] = sb[cur][t + 1024];
}

// ---------------- fill CSR entries (warp per row, ballot compaction) ----------------
__global__ void fill_kernel(const float* __restrict__ W) {
    int gw   = (blockIdx.x * blockDim.x + threadIdx.x) >> 5;
    int lane = threadIdx.x & 31;
    if (gw >= NN) return;
    const float* row = W + (size_t)gw * NN;
    int p = g_rowptr[gw];
    for (int m0 = 0; m0 < NN; m0 += 32) {
        float w = row[m0 + lane];
        unsigned msk = __ballot_sync(0xffffffffu, w != 0.0f);
        if (w != 0.0f) {
            int off = p + __popc(msk & ((1u << lane) - 1u));
            g_ent[off] = make_float2(w, __int_as_float(m0 + lane));
        }
        p += __popc(msk);
    }
}

// ---------------- drive GEMM: C[M=16384, N=2048] = X@Win^T + FB@Wfb^T ----------------
// Classic 128x128x8 SIMT fp32 tile, 256 threads, 8x8 per thread, double-buffered smem.
__global__ void __launch_bounds__(256) drive_gemm(
    const float* __restrict__ X, const float* __restrict__ FB,
    const float* __restrict__ Win, const float* __restrict__ Wfb,
    float* __restrict__ C)
{
    const int K = DD;
    __shared__ float As[2][8][128];
    __shared__ float Bs[2][8][128];
    int tid     = threadIdx.x;
    int colBase = blockIdx.x * 128;
    int rowBase = blockIdx.y * 128;
    int tx = tid & 15, ty = tid >> 4;
    int lr = tid >> 1;           // load row within tile (0..127)
    int lc = (tid & 1) * 4;      // k sub-offset (0 or 4)

    float acc[8][8];
#pragma unroll
    for (int i = 0; i < 8; i++)
#pragma unroll
        for (int j = 0; j < 8; j++) acc[i][j] = 0.0f;

    for (int pair = 0; pair < 2; ++pair) {
        const float* A  = pair ? FB  : X;    // [M][K] row-major
        const float* Bm = pair ? Wfb : Win;  // [N][K] row-major
        const float* ap = A  + (size_t)(rowBase + lr) * K + lc;
        const float* bp = Bm + (size_t)(colBase + lr) * K + lc;

        __syncthreads();  // protect smem from previous pair's readers
        float4 a = *(const float4*)ap;
        float4 b = *(const float4*)bp;
        int buf = 0;
        As[0][lc + 0][lr] = a.x; As[0][lc + 1][lr] = a.y;
        As[0][lc + 2][lr] = a.z; As[0][lc + 3][lr] = a.w;
        Bs[0][lc + 0][lr] = b.x; Bs[0][lc + 1][lr] = b.y;
        Bs[0][lc + 2][lr] = b.z; Bs[0][lc + 3][lr] = b.w;
        __syncthreads();

        const int KT = K / 8;  // 64
        for (int kt = 0; kt < KT; ++kt) {
            float4 an, bn;
            bool more = (kt + 1 < KT);
            if (more) {
                an = *(const float4*)(ap + (kt + 1) * 8);
                bn = *(const float4*)(bp + (kt + 1) * 8);
            }
#pragma unroll
            for (int kk = 0; kk < 8; ++kk) {
                float4 a0 = *(const float4*)&As[buf][kk][ty * 8];
                float4 a1 = *(const float4*)&As[buf][kk][ty * 8 + 4];
                float4 b0 = *(const float4*)&Bs[buf][kk][tx * 8];
                float4 b1 = *(const float4*)&Bs[buf][kk][tx * 8 + 4];
                float av[8] = {a0.x, a0.y, a0.z, a0.w, a1.x, a1.y, a1.z, a1.w};
                float bv[8] = {b0.x, b0.y, b0.z, b0.w, b1.x, b1.y, b1.z, b1.w};
#pragma unroll
                for (int i = 0; i < 8; i++)
#pragma unroll
                    for (int j = 0; j < 8; j++)
                        acc[i][j] = fmaf(av[i], bv[j], acc[i][j]);
            }
            if (more) {
                int nb = buf ^ 1;
                As[nb][lc + 0][lr] = an.x; As[nb][lc + 1][lr] = an.y;
                As[nb][lc + 2][lr] = an.z; As[nb][lc + 3][lr] = an.w;
                Bs[nb][lc + 0][lr] = bn.x; Bs[nb][lc + 1][lr] = bn.y;
                Bs[nb][lc + 2][lr] = bn.z; Bs[nb][lc + 3][lr] = bn.w;
                __syncthreads();
                buf = nb;
            }
        }
    }

#pragma unroll
    for (int i = 0; i < 8; i++) {
        size_t o = (size_t)(rowBase + ty * 8 + i) * NN + colBase + tx * 8;
        float4 v0 = make_float4(acc[i][0], acc[i][1], acc[i][2], acc[i][3]);
        float4 v1 = make_float4(acc[i][4], acc[i][5], acc[i][6], acc[i][7]);
        *(float4*)&C[o]     = v0;
        *(float4*)&C[o + 4] = v1;
    }
}

// ---------------- persistent recurrence kernel ----------------
// 64 CTAs x 512 threads. Half-warp layout: 16 lanes = 16 batches of ONE row
// -> W entry loads uniform per half-warp, state loads 64B-coalesced.
// Per-step grid-wide sync via monotonic counter (release atomic + acquire spin).
__global__ void __launch_bounds__(RTHREADS, 1) recur_kernel(float* __restrict__ out) {
    int tid  = threadIdx.x;
    int w    = tid >> 5;
    int lane = tid & 31;
    int rsel = lane >> 4;
    int b    = lane & 15;
    int row  = blockIdx.x * (RTHREADS / 16) + w * 2 + rsel;

    int start = g_rowptr[row];
    int len   = g_rowptr[row + 1] - start;
    int olen  = __shfl_xor_sync(0xffffffffu, len, 16);
    int lmax  = len > olen ? len : olen;
    const float2* ent = g_ent + start;

    size_t oidx = ((size_t)b * SS) * NN + row;

    for (int s = 0; s < SS; ++s) {
        const float* cur = g_state[s & 1];
        float*       nxt = g_state[(s & 1) ^ 1];

        float acc = out[oidx + (size_t)s * NN];  // drive (written by GEMM)

#pragma unroll 8
        for (int j = 0; j < lmax; ++j) {
            int jj = (j < len) ? j : 0;
            float2 e = ent[jj];
            // L1 is not coherent across SMs -> bypass for state reads
            float sv = __ldcg(&cur[(__float_as_int(e.y) << 4) + b]);
            acc = (j < len) ? fmaf(e.x, sv, acc) : acc;
        }

        float ns = tanhf(acc);
        nxt[(row << 4) + b]       = ns;
        out[oidx + (size_t)s * NN] = ns;

        __syncthreads();
        if (s + 1 < SS) {
            if (tid == 0) {
                __threadfence();                       // release prior stores (gpu scope)
                atomicAdd(&g_barrier, 1u);
                unsigned target = (unsigned)gridDim.x * (unsigned)(s + 1);
                unsigned v;
                do {
                    asm volatile("ld.acquire.gpu.u32 %0, [%1];"
                                 : "=r"(v) : "l"(&g_barrier) : "memory");
                } while (v < target);
            }
            __syncthreads();
        }
    }
}

// ---------------- launch ----------------
extern "C" void kernel_launch(void* const* d_in, const int* in_sizes, int n_in,
                              void* d_out, int out_size) {
    const float* x    = (const float*)d_in[0];
    const float* fb   = (const float*)d_in[1];
    const float* init = (const float*)d_in[2];
    const float* Wres = (const float*)d_in[3];
    const float* Win  = (const float*)d_in[4];
    const float* Wfb  = (const float*)d_in[5];
    float* out = (float*)d_out;

    init_kernel<<<(NN * BB + 255) / 256, 256>>>(init);
    count_kernel<<<64, 1024>>>(Wres);
    scan_kernel<<<1, 1024>>>();
    fill_kernel<<<64, 1024>>>(Wres);
    drive_gemm<<<dim3(NN / 128, (BB * SS) / 128), 256>>>(x, fb, Win, Wfb, out);
    recur_kernel<<<RCTAS, RTHREADS>>>(out);
}